// round 5
// baseline (speedup 1.0000x reference)
#include <cuda_runtime.h>
#include <cuda_bf16.h>
#include <math.h>

// Problem constants
#define BB 16
#define NN 512
#define INF_ 256
#define OUTF 256
#define HH 8
#define NET 50

// Scratch (device globals; no allocation allowed)
__device__ float g_Wh[BB * NN * OUTF];     // 8.4 MB
__device__ float g_s1[BB * NN * HH];
__device__ float g_s2[BB * NN * HH];

// ---------------------------------------------------------------------------
// Kernel A: Wh = x @ W   (M=8192, K=256, N=256). Simple 32x32 tiling.
// ---------------------------------------------------------------------------
__global__ __launch_bounds__(256) void gemm_kernel(const float* __restrict__ x,
                                                   const float* __restrict__ W) {
    __shared__ float sA[32][33];   // [local_row][local_k]
    __shared__ float sB[32][33];   // [local_k][local_col]
    int tx = threadIdx.x & 31;
    int ty = threadIdx.x >> 5;     // 0..7
    int row0 = blockIdx.y * 32;
    int col0 = blockIdx.x * 32;
    float c0 = 0.f, c1 = 0.f, c2 = 0.f, c3 = 0.f;
    for (int kt = 0; kt < INF_ / 32; kt++) {
#pragma unroll
        for (int q = 0; q < 4; q++) {
            int r = ty + q * 8;    // covers 0..31
            sA[r][tx] = x[(size_t)(row0 + r) * INF_ + kt * 32 + tx];
            sB[r][tx] = W[(size_t)(kt * 32 + r) * OUTF + col0 + tx];
        }
        __syncthreads();
#pragma unroll
        for (int k = 0; k < 32; k++) {
            float b = sB[k][tx];
            c0 = fmaf(sA[ty     ][k], b, c0);
            c1 = fmaf(sA[ty +  8][k], b, c1);
            c2 = fmaf(sA[ty + 16][k], b, c2);
            c3 = fmaf(sA[ty + 24][k], b, c3);
        }
        __syncthreads();
    }
    g_Wh[(size_t)(row0 + ty     ) * OUTF + col0 + tx] = c0;
    g_Wh[(size_t)(row0 + ty +  8) * OUTF + col0 + tx] = c1;
    g_Wh[(size_t)(row0 + ty + 16) * OUTF + col0 + tx] = c2;
    g_Wh[(size_t)(row0 + ty + 24) * OUTF + col0 + tx] = c3;
}

// ---------------------------------------------------------------------------
// Kernel B: s1[b,n,h] = dot(Wh[b,n,h,:], a1);  s2 likewise. One thread per (n,h).
// ---------------------------------------------------------------------------
__global__ __launch_bounds__(256) void s_kernel(const float* __restrict__ a1,
                                                const float* __restrict__ a2) {
    int t = blockIdx.x * blockDim.x + threadIdx.x;  // 0 .. BB*NN*HH-1
    if (t >= BB * NN * HH) return;
    int h = t & 7;
    int n = t >> 3;
    const float* row = g_Wh + (size_t)n * OUTF + h * 32;
    float t1 = 0.f, t2 = 0.f;
#pragma unroll
    for (int d = 0; d < 32; d++) {
        float v = row[d];
        t1 = fmaf(v, a1[d], t1);
        t2 = fmaf(v, a2[d], t2);
    }
    g_s1[t] = t1;
    g_s2[t] = t2;
}

// ---------------------------------------------------------------------------
// Kernel C (BRUTE FORCE, correctness-first): one warp per (b, i) row.
// lane = d within a head; serial loop over j. All control values (adj, et,
// s2, emb, p) are warp-uniform scalars; only Wh reads are per-lane (coalesced
// 128B). No SMEM transposes, no cross-warp staging of per-warp data.
// softmax denominator is lane-uniform -> no reduction needed.
// ---------------------------------------------------------------------------
__global__ __launch_bounds__(256) void attn_bf(const int* __restrict__ adj,
                                               const int* __restrict__ et,
                                               const float* __restrict__ emb,
                                               const float* __restrict__ gamma,
                                               const float* __restrict__ beta,
                                               float* __restrict__ out) {
    __shared__ float sEmb[NET * HH];    // 400 floats
    __shared__ float sS2[NN * HH];      // 4096 floats (one batch's s2)
    int tid = threadIdx.x;
    int w = tid >> 5, ln = tid & 31;
    int b = blockIdx.x >> 6;            // 64 blocks per batch
    int i = ((blockIdx.x & 63) << 3) + w;   // 8 rows per block

    for (int q = tid; q < NET * HH; q += 256) sEmb[q] = emb[q];
    for (int q = tid; q < NN * HH; q += 256) sS2[q] = g_s2[(size_t)b * NN * HH + q];
    __syncthreads();

    float s1h[HH];
    const float* s1p = g_s1 + (size_t)(b * NN + i) * HH;
#pragma unroll
    for (int h = 0; h < HH; h++) s1h[h] = s1p[h];

    float acc[HH], lsum[HH];
#pragma unroll
    for (int h = 0; h < HH; h++) { acc[h] = 0.f; lsum[h] = 0.f; }

    const int* adjrow = adj + (size_t)(b * NN + i) * NN;
    const int* etrow  = et  + (size_t)(b * NN + i) * NN;
    const float* WhB  = g_Wh + (size_t)b * NN * OUTF + ln;

    for (int j = 0; j < NN; j++) {
        int av = adjrow[j];             // warp-uniform
        if (av == 0) continue;          // exact: p would be 0
        int eb = etrow[j] * HH;
        const float* whr = WhB + (size_t)j * OUTF;
#pragma unroll
        for (int h = 0; h < HH; h++) {
            float e = s1h[h] + sS2[j * HH + h] + sEmb[eb + h];
            e = (e > 0.f) ? e : 0.2f * e;           // leaky relu 0.2
            float p = __expf(e);                    // |e| <~ 12: overflow-safe
            lsum[h] += p;
            acc[h] = fmaf(p, whr[h << 5], acc[h]);  // Wh[b,j,h*32+ln]
        }
    }

    // y = softmax-weighted sum; lsum is identical across lanes (uniform p's)
    float y[HH];
    float s = 0.f;
#pragma unroll
    for (int h = 0; h < HH; h++) { y[h] = acc[h] / lsum[h]; s += y[h]; }
    s += __shfl_xor_sync(0xffffffffu, s, 16);
    s += __shfl_xor_sync(0xffffffffu, s, 8);
    s += __shfl_xor_sync(0xffffffffu, s, 4);
    s += __shfl_xor_sync(0xffffffffu, s, 2);
    s += __shfl_xor_sync(0xffffffffu, s, 1);
    float mu = s * 0.00390625f;         // /256
    float vs = 0.f;
#pragma unroll
    for (int h = 0; h < HH; h++) { float d = y[h] - mu; vs = fmaf(d, d, vs); }
    vs += __shfl_xor_sync(0xffffffffu, vs, 16);
    vs += __shfl_xor_sync(0xffffffffu, vs, 8);
    vs += __shfl_xor_sync(0xffffffffu, vs, 4);
    vs += __shfl_xor_sync(0xffffffffu, vs, 2);
    vs += __shfl_xor_sync(0xffffffffu, vs, 1);
    float rstd = rsqrtf(vs * 0.00390625f + 1e-5f);

    float* op = out + (size_t)(b * NN + i) * OUTF;
#pragma unroll
    for (int h = 0; h < HH; h++) {
        float g = gamma[(h << 5) + ln];
        float be = beta[(h << 5) + ln];
        float o = fmaf((y[h] - mu) * rstd, g, be);
        o = (o > 0.f) ? o : expm1f(o);              // ELU
        op[(h << 5) + ln] = o;
    }
}

// ---------------------------------------------------------------------------
extern "C" void kernel_launch(void* const* d_in, const int* in_sizes, int n_in,
                              void* d_out, int out_size) {
    const float* x     = (const float*)d_in[0];
    const int*   adj   = (const int*)  d_in[1];
    const int*   etyp  = (const int*)  d_in[2];
    const float* W     = (const float*)d_in[3];
    const float* a1    = (const float*)d_in[4];
    const float* a2    = (const float*)d_in[5];
    const float* emb   = (const float*)d_in[6];
    const float* gamma = (const float*)d_in[7];
    const float* beta  = (const float*)d_in[8];
    float* out = (float*)d_out;

    dim3 gg(OUTF / 32, (BB * NN) / 32);
    gemm_kernel<<<gg, 256>>>(x, W);
    s_kernel<<<(BB * NN * HH + 255) / 256, 256>>>(a1, a2);
    attn_bf<<<BB * 64, 256>>>(adj, etyp, emb, gamma, beta, out);
}

// round 6
// speedup vs baseline: 2.1010x; 2.1010x over previous
#include <cuda_runtime.h>
#include <cuda_bf16.h>
#include <math.h>

// Problem constants
#define BB 16
#define NN 512
#define INF_ 256
#define OUTF 256
#define HH 8
#define NET 50

#define TI 32   // i-rows per block (attention)
#define TJ 32   // j-cols per tile
#define IPW 4   // i rows per warp (8 warps)

// Scratch (device globals; no allocation allowed)
__device__ float g_Wh[BB * NN * OUTF];     // 8.4 MB
__device__ float g_s1[BB * NN * HH];
__device__ float g_s2[BB * NN * HH];

// ---------------------------------------------------------------------------
// Kernel A: Wh = x @ W   (M=8192, K=256, N=256). 64x64 tile, 4x4 micro.
// ---------------------------------------------------------------------------
__global__ __launch_bounds__(256) void gemm_kernel(const float* __restrict__ x,
                                                   const float* __restrict__ W) {
    __shared__ float sA[16][68];   // transposed A tile [k][row]
    __shared__ float sB[16][64];   // [k][col]
    int tid = threadIdx.x;
    int row0 = blockIdx.y * 64;
    int col0 = blockIdx.x * 64;
    int ty = tid >> 4, tx = tid & 15;
    float c[4][4] = {};
    for (int kt = 0; kt < 16; kt++) {
        {   // A tile (transpose on store)
            int r = tid >> 2, kk = (tid & 3) << 2;
            float4 v = *(const float4*)(x + (size_t)(row0 + r) * INF_ + kt * 16 + kk);
            sA[kk + 0][r] = v.x; sA[kk + 1][r] = v.y;
            sA[kk + 2][r] = v.z; sA[kk + 3][r] = v.w;
        }
        {   // B tile
            int r = tid >> 4, c4 = (tid & 15) << 2;
            *(float4*)&sB[r][c4] = *(const float4*)(W + (size_t)(kt * 16 + r) * OUTF + col0 + c4);
        }
        __syncthreads();
#pragma unroll
        for (int k = 0; k < 16; k++) {
            float4 a  = *(const float4*)(&sA[k][ty << 2]);
            float4 bb = *(const float4*)(&sB[k][tx << 2]);
            c[0][0] = fmaf(a.x, bb.x, c[0][0]); c[0][1] = fmaf(a.x, bb.y, c[0][1]);
            c[0][2] = fmaf(a.x, bb.z, c[0][2]); c[0][3] = fmaf(a.x, bb.w, c[0][3]);
            c[1][0] = fmaf(a.y, bb.x, c[1][0]); c[1][1] = fmaf(a.y, bb.y, c[1][1]);
            c[1][2] = fmaf(a.y, bb.z, c[1][2]); c[1][3] = fmaf(a.y, bb.w, c[1][3]);
            c[2][0] = fmaf(a.z, bb.x, c[2][0]); c[2][1] = fmaf(a.z, bb.y, c[2][1]);
            c[2][2] = fmaf(a.z, bb.z, c[2][2]); c[2][3] = fmaf(a.z, bb.w, c[2][3]);
            c[3][0] = fmaf(a.w, bb.x, c[3][0]); c[3][1] = fmaf(a.w, bb.y, c[3][1]);
            c[3][2] = fmaf(a.w, bb.z, c[3][2]); c[3][3] = fmaf(a.w, bb.w, c[3][3]);
        }
        __syncthreads();
    }
#pragma unroll
    for (int i = 0; i < 4; i++) {
        float4 v = make_float4(c[i][0], c[i][1], c[i][2], c[i][3]);
        *(float4*)(g_Wh + (size_t)(row0 + (ty << 2) + i) * OUTF + col0 + (tx << 2)) = v;
    }
}

// ---------------------------------------------------------------------------
// Kernel B: s1[b,n,h] = dot(Wh[b,n,h,:], a1);  s2 likewise. One thread per (n,h).
// ---------------------------------------------------------------------------
__global__ __launch_bounds__(256) void s_kernel(const float* __restrict__ a1,
                                                const float* __restrict__ a2) {
    int t = blockIdx.x * blockDim.x + threadIdx.x;  // 0 .. BB*NN*HH-1
    if (t >= BB * NN * HH) return;
    int h = t & 7;
    int n = t >> 3;
    const float* row = g_Wh + (size_t)n * OUTF + h * 32;
    float t1 = 0.f, t2 = 0.f;
#pragma unroll
    for (int d = 0; d < 32; d++) {
        float v = row[d];
        t1 = fmaf(v, a1[d], t1);
        t2 = fmaf(v, a2[d], t2);
    }
    g_s1[t] = t1;
    g_s2[t] = t2;
}

// ---------------------------------------------------------------------------
// Kernel C: fused attention + softmax + aggregation + LayerNorm + ELU.
// One block = (b, 32 i-rows). 8 warps; warp handles 4 i-rows, all heads.
// Score phase: lane = j. Accumulate phase: lane = d (via warp-private SMEM
// p transpose). sP region is warp-private -> __syncwarp between phases.
// ---------------------------------------------------------------------------
#define SM_WH   0                   // 8192 f  (Wh tile: 32 j-rows x 256 feats)
#define SM_P    8192                // 8192 f  (p: [warp][ii][h][j])
#define SM_S2   16384               // 288 f   (32 x stride 9)
#define SM_S1   16672               // 256 f
#define SM_EMB  16928               // 450 f   (50 x stride 9)
#define SM_ADJ  17378               // 1024 i
#define SM_ET   18402               // 1024 i
#define SMEM_FLOATS 19426
#define SMEM_BYTES (SMEM_FLOATS * 4)

__global__ __launch_bounds__(256, 2)
void attn_kernel(const int* __restrict__ adj, const int* __restrict__ et,
                 const float* __restrict__ emb, const float* __restrict__ gamma,
                 const float* __restrict__ beta, float* __restrict__ out) {
    extern __shared__ float sm[];
    float* sWh  = sm + SM_WH;
    float* sP   = sm + SM_P;
    float* sS2  = sm + SM_S2;
    float* sS1  = sm + SM_S1;
    float* sEmb = sm + SM_EMB;
    int*   sAdj = (int*)(sm + SM_ADJ);
    int*   sEt  = (int*)(sm + SM_ET);

    int tid = threadIdx.x;
    int w = tid >> 5, ln = tid & 31;
    int b  = blockIdx.x >> 4;
    int i0 = (blockIdx.x & 15) * TI;

    // one-time loads: s1 rows (exactly 256 vals) and FULL edge embedding
    // (400 vals > blockDim -> MUST be a grid-stride loop; this was the R1-3 bug)
    sS1[tid] = g_s1[(size_t)(b * NN + i0) * HH + tid];
    for (int q = tid; q < NET * HH; q += 256)
        sEmb[(q >> 3) * 9 + (q & 7)] = emb[q];

    float acc[IPW][HH];
    float lsum[IPW][HH];
#pragma unroll
    for (int ii = 0; ii < IPW; ii++)
#pragma unroll
        for (int h = 0; h < HH; h++) { acc[ii][h] = 0.f; lsum[ii][h] = 0.f; }

    for (int jt = 0; jt < NN / TJ; jt++) {
        int j0 = jt * TJ;
        __syncthreads();
        // stage Wh tile [32 j][256 f]
        {
            const float4* src = (const float4*)(g_Wh + (size_t)(b * NN + j0) * OUTF);
            float4* dst = (float4*)sWh;
#pragma unroll
            for (int q = 0; q < 8; q++) dst[q * 256 + tid] = src[q * 256 + tid];
        }
        // s2 tile (stride 9)
        sS2[(tid >> 3) * 9 + (tid & 7)] = g_s2[(size_t)(b * NN + j0) * HH + tid];
        // adj / edge_type tiles [32 i][32 j]
#pragma unroll
        for (int q = 0; q < 4; q++) {
            int lin = q * 256 + tid;
            int i = lin >> 5, j = lin & 31;
            size_t gofs = (size_t)(b * NN + i0 + i) * NN + j0 + j;
            sAdj[lin] = adj[gofs];
            sEt[lin]  = et[gofs];
        }
        __syncthreads();

        // -------- score phase: lane = j --------
#pragma unroll
        for (int ii = 0; ii < IPW; ii++) {
            int il = (w << 2) + ii;
            int adjv = sAdj[(il << 5) + ln];
            int eb   = sEt[(il << 5) + ln] * 9;
            const float* s1p = sS1 + (il << 3);
            float* pdst = sP + (w << 10) + (ii << 8);   // [w][ii][h][32]
#pragma unroll
            for (int h = 0; h < HH; h++) {
                float e = s1p[h] + sS2[ln * 9 + h] + sEmb[eb + h];
                e = fmaf(0.2f, fminf(e, 0.f), fmaxf(e, 0.f));   // leaky relu 0.2
                float p = (adjv != 0) ? __expf(e) : 0.0f;       // |e|<~12: safe
                lsum[ii][h] += p;
                pdst[(h << 5) + ln] = p;
            }
        }
        __syncwarp();   // sP region is warp-private

        // -------- accumulate phase: lane = d --------
        const float* pw = sP + (w << 10);
#pragma unroll
        for (int h = 0; h < HH; h++) {
            const float* whc = sWh + (h << 5) + ln;
            const float* p0p = pw + (h << 5);
            const float* p1p = pw + 256 + (h << 5);
            const float* p2p = pw + 512 + (h << 5);
            const float* p3p = pw + 768 + (h << 5);
#pragma unroll
            for (int j4 = 0; j4 < 8; j4++) {
                float4 q0 = *(const float4*)(p0p + (j4 << 2));
                float4 q1 = *(const float4*)(p1p + (j4 << 2));
                float4 q2 = *(const float4*)(p2p + (j4 << 2));
                float4 q3 = *(const float4*)(p3p + (j4 << 2));
                float w0 = whc[((j4 << 2) + 0) * OUTF];
                float w1 = whc[((j4 << 2) + 1) * OUTF];
                float w2 = whc[((j4 << 2) + 2) * OUTF];
                float w3 = whc[((j4 << 2) + 3) * OUTF];
                acc[0][h] = fmaf(q0.x, w0, acc[0][h]);
                acc[1][h] = fmaf(q1.x, w0, acc[1][h]);
                acc[2][h] = fmaf(q2.x, w0, acc[2][h]);
                acc[3][h] = fmaf(q3.x, w0, acc[3][h]);
                acc[0][h] = fmaf(q0.y, w1, acc[0][h]);
                acc[1][h] = fmaf(q1.y, w1, acc[1][h]);
                acc[2][h] = fmaf(q2.y, w1, acc[2][h]);
                acc[3][h] = fmaf(q3.y, w1, acc[3][h]);
                acc[0][h] = fmaf(q0.z, w2, acc[0][h]);
                acc[1][h] = fmaf(q1.z, w2, acc[1][h]);
                acc[2][h] = fmaf(q2.z, w2, acc[2][h]);
                acc[3][h] = fmaf(q3.z, w2, acc[3][h]);
                acc[0][h] = fmaf(q0.w, w3, acc[0][h]);
                acc[1][h] = fmaf(q1.w, w3, acc[1][h]);
                acc[2][h] = fmaf(q2.w, w3, acc[2][h]);
                acc[3][h] = fmaf(q3.w, w3, acc[3][h]);
            }
        }
    }

    // -------- softmax denominators (reduce over lanes = j) --------
#pragma unroll
    for (int ii = 0; ii < IPW; ii++)
#pragma unroll
        for (int h = 0; h < HH; h++) {
            float v = lsum[ii][h];
            v += __shfl_xor_sync(0xffffffffu, v, 16);
            v += __shfl_xor_sync(0xffffffffu, v, 8);
            v += __shfl_xor_sync(0xffffffffu, v, 4);
            v += __shfl_xor_sync(0xffffffffu, v, 2);
            v += __shfl_xor_sync(0xffffffffu, v, 1);
            lsum[ii][h] = 1.0f / v;
        }

    float gr[HH], br[HH];
#pragma unroll
    for (int h = 0; h < HH; h++) {
        gr[h] = gamma[(h << 5) + ln];
        br[h] = beta[(h << 5) + ln];
    }

    // -------- LayerNorm + ELU + store --------
    int ibase = b * NN + i0 + (w << 2);
#pragma unroll
    for (int ii = 0; ii < IPW; ii++) {
        float y[HH];
        float s = 0.f;
#pragma unroll
        for (int h = 0; h < HH; h++) { y[h] = acc[ii][h] * lsum[ii][h]; s += y[h]; }
        s += __shfl_xor_sync(0xffffffffu, s, 16);
        s += __shfl_xor_sync(0xffffffffu, s, 8);
        s += __shfl_xor_sync(0xffffffffu, s, 4);
        s += __shfl_xor_sync(0xffffffffu, s, 2);
        s += __shfl_xor_sync(0xffffffffu, s, 1);
        float mu = s * 0.00390625f;   // /256
        float vs = 0.f;
#pragma unroll
        for (int h = 0; h < HH; h++) { float d = y[h] - mu; vs = fmaf(d, d, vs); }
        vs += __shfl_xor_sync(0xffffffffu, vs, 16);
        vs += __shfl_xor_sync(0xffffffffu, vs, 8);
        vs += __shfl_xor_sync(0xffffffffu, vs, 4);
        vs += __shfl_xor_sync(0xffffffffu, vs, 2);
        vs += __shfl_xor_sync(0xffffffffu, vs, 1);
        float rstd = rsqrtf(vs * 0.00390625f + 1e-5f);
        float* op = out + (size_t)(ibase + ii) * OUTF;
#pragma unroll
        for (int h = 0; h < HH; h++) {
            float o = fmaf((y[h] - mu) * rstd, gr[h], br[h]);
            o = (o > 0.f) ? o : expm1f(o);
            op[(h << 5) + ln] = o;
        }
    }
}

// ---------------------------------------------------------------------------
extern "C" void kernel_launch(void* const* d_in, const int* in_sizes, int n_in,
                              void* d_out, int out_size) {
    const float* x     = (const float*)d_in[0];
    const int*   adj   = (const int*)  d_in[1];
    const int*   etyp  = (const int*)  d_in[2];
    const float* W     = (const float*)d_in[3];
    const float* a1    = (const float*)d_in[4];
    const float* a2    = (const float*)d_in[5];
    const float* emb   = (const float*)d_in[6];
    const float* gamma = (const float*)d_in[7];
    const float* beta  = (const float*)d_in[8];
    float* out = (float*)d_out;

    dim3 gg(OUTF / 64, (BB * NN) / 64);
    gemm_kernel<<<gg, 256>>>(x, W);
    s_kernel<<<(BB * NN * HH + 255) / 256, 256>>>(a1, a2);
    cudaFuncSetAttribute(attn_kernel, cudaFuncAttributeMaxDynamicSharedMemorySize, SMEM_BYTES);
    attn_kernel<<<BB * (NN / TI), 256, SMEM_BYTES>>>(adj, etyp, emb, gamma, beta, out);
}

// round 9
// speedup vs baseline: 2.3391x; 1.1133x over previous
#include <cuda_runtime.h>
#include <cuda_bf16.h>
#include <math.h>
#include <cstdint>

// Problem constants
#define BB 16
#define NN 512
#define INF_ 256
#define OUTF 256
#define HH 8
#define NET 50

#define TI 32   // i-rows per block (attention)
#define TJ 32   // j-cols per tile
#define IPW 4   // i rows per warp (8 warps)

// Scratch (device globals; no allocation allowed)
__device__ float g_Wh[BB * NN * OUTF];     // 8.4 MB
__device__ float g_s1[BB * NN * HH];
__device__ float g_s2[BB * NN * HH];

// cp.async helpers (LDGSTS on sm_103a)
#define CP_ASYNC16(dst_u32, src) \
    asm volatile("cp.async.cg.shared.global [%0], [%1], 16;\n" :: "r"(dst_u32), "l"(src))
#define CP_COMMIT() asm volatile("cp.async.commit_group;\n")
#define CP_WAIT1()  asm volatile("cp.async.wait_group 1;\n")
#define CP_WAIT0()  asm volatile("cp.async.wait_group 0;\n")

// ---------------------------------------------------------------------------
// Kernel A: Wh = x @ W   (M=8192, K=256, N=256). 128x64 tile, 8x4 microtile.
// ---------------------------------------------------------------------------
__global__ __launch_bounds__(256) void gemm_kernel(const float* __restrict__ x,
                                                   const float* __restrict__ W) {
    __shared__ float sA[16][132];   // [k][m] transposed, pad 132 (528B rows: 16B-mult)
    __shared__ float sB[16][64];    // [k][n]
    int tid = threadIdx.x;
    int row0 = blockIdx.y * 128;
    int col0 = blockIdx.x * 64;
    int tx = tid & 15, ty = tid >> 4;

    // staging maps
    int ar = tid >> 2;              // A row within half-tile
    int ac4 = (tid & 3) << 2;       // k-chunk within row
    int br = tid >> 4;              // B: k row 0..15
    int bc4 = (tid & 15) << 2;      // col chunk

    float acc0[4][4] = {}, acc1[4][4] = {};
    float4 pa0, pa1, pb;

    // prefetch k-tile 0
    pa0 = *(const float4*)(x + (size_t)(row0 + ar) * INF_ + ac4);
    pa1 = *(const float4*)(x + (size_t)(row0 + 64 + ar) * INF_ + ac4);
    pb  = *(const float4*)(W + (size_t)br * OUTF + col0 + bc4);

    for (int kt = 0; kt < 16; kt++) {
        __syncthreads();
        // store staged tile
        sA[ac4 + 0][ar] = pa0.x; sA[ac4 + 1][ar] = pa0.y;
        sA[ac4 + 2][ar] = pa0.z; sA[ac4 + 3][ar] = pa0.w;
        sA[ac4 + 0][64 + ar] = pa1.x; sA[ac4 + 1][64 + ar] = pa1.y;
        sA[ac4 + 2][64 + ar] = pa1.z; sA[ac4 + 3][64 + ar] = pa1.w;
        *(float4*)&sB[br][bc4] = pb;
        __syncthreads();
        // prefetch next k-tile (overlaps compute)
        if (kt < 15) {
            int k0 = (kt + 1) * 16;
            pa0 = *(const float4*)(x + (size_t)(row0 + ar) * INF_ + k0 + ac4);
            pa1 = *(const float4*)(x + (size_t)(row0 + 64 + ar) * INF_ + k0 + ac4);
            pb  = *(const float4*)(W + (size_t)(k0 + br) * OUTF + col0 + bc4);
        }
#pragma unroll
        for (int k = 0; k < 16; k++) {
            float4 aL = *(const float4*)(&sA[k][ty << 2]);
            float4 aH = *(const float4*)(&sA[k][64 + (ty << 2)]);
            float4 b  = *(const float4*)(&sB[k][tx << 2]);
            float av[4] = {aL.x, aL.y, aL.z, aL.w};
            float ah[4] = {aH.x, aH.y, aH.z, aH.w};
            float bv[4] = {b.x, b.y, b.z, b.w};
#pragma unroll
            for (int i = 0; i < 4; i++)
#pragma unroll
                for (int j = 0; j < 4; j++) {
                    acc0[i][j] = fmaf(av[i], bv[j], acc0[i][j]);
                    acc1[i][j] = fmaf(ah[i], bv[j], acc1[i][j]);
                }
        }
    }
#pragma unroll
    for (int i = 0; i < 4; i++) {
        float4 v0 = make_float4(acc0[i][0], acc0[i][1], acc0[i][2], acc0[i][3]);
        float4 v1 = make_float4(acc1[i][0], acc1[i][1], acc1[i][2], acc1[i][3]);
        *(float4*)(g_Wh + (size_t)(row0 + (ty << 2) + i) * OUTF + col0 + (tx << 2)) = v0;
        *(float4*)(g_Wh + (size_t)(row0 + 64 + (ty << 2) + i) * OUTF + col0 + (tx << 2)) = v1;
    }
}

// ---------------------------------------------------------------------------
// Kernel B: s1[b,n,h] = dot(Wh[b,n,h,:], a1);  s2 likewise. One thread per (n,h).
// ---------------------------------------------------------------------------
__global__ __launch_bounds__(256) void s_kernel(const float* __restrict__ a1,
                                                const float* __restrict__ a2) {
    int t = blockIdx.x * blockDim.x + threadIdx.x;  // 0 .. BB*NN*HH-1
    if (t >= BB * NN * HH) return;
    int h = t & 7;
    int n = t >> 3;
    const float4* row = (const float4*)(g_Wh + (size_t)n * OUTF + h * 32);
    const float4* A1 = (const float4*)a1;
    const float4* A2 = (const float4*)a2;
    float t1 = 0.f, t2 = 0.f;
#pragma unroll
    for (int d4 = 0; d4 < 8; d4++) {
        float4 v = row[d4];
        float4 w1 = A1[d4];
        float4 w2 = A2[d4];
        t1 = fmaf(v.x, w1.x, t1); t1 = fmaf(v.y, w1.y, t1);
        t1 = fmaf(v.z, w1.z, t1); t1 = fmaf(v.w, w1.w, t1);
        t2 = fmaf(v.x, w2.x, t2); t2 = fmaf(v.y, w2.y, t2);
        t2 = fmaf(v.z, w2.z, t2); t2 = fmaf(v.w, w2.w, t2);
    }
    g_s1[t] = t1;
    g_s2[t] = t2;
}

// ---------------------------------------------------------------------------
// Kernel C: fused attention + softmax + aggregation + LayerNorm + ELU.
// One block = (b, 32 i-rows). 8 warps; warp handles 4 i-rows, all heads.
// Wh tiles double-buffered via cp.async; adj/et/s2 prefetched into registers.
// ---------------------------------------------------------------------------
#define SM_WH   0                   // 2 x 8192 f (double-buffered Wh tiles)
#define SM_P    16384               // 8192 f  (p: [warp][ii][h][j])
#define SM_S2   24576               // 288 f   (32 x stride 9)
#define SM_S1   24864               // 256 f
#define SM_EMB  25120               // 450 f   (50 x stride 9)
#define SM_ADJ  25572               // 1024 i  (16B-ALIGNED: 25572*4 % 16 == 0)
#define SM_ET   26596               // 1024 i  (16B-ALIGNED)
#define SMEM_FLOATS 27620
#define SMEM_BYTES (SMEM_FLOATS * 4)    // 110480 B -> 2 blocks/SM

__global__ __launch_bounds__(256, 2)
void attn_kernel(const int* __restrict__ adj, const int* __restrict__ et,
                 const float* __restrict__ emb, const float* __restrict__ gamma,
                 const float* __restrict__ beta, float* __restrict__ out) {
    extern __shared__ float sm[];
    float* sWh  = sm + SM_WH;       // [2][8192]
    float* sP   = sm + SM_P;
    float* sS2  = sm + SM_S2;
    float* sS1  = sm + SM_S1;
    float* sEmb = sm + SM_EMB;
    int*   sAdj = (int*)(sm + SM_ADJ);
    int*   sEt  = (int*)(sm + SM_ET);

    int tid = threadIdx.x;
    int w = tid >> 5, ln = tid & 31;
    int b  = blockIdx.x >> 4;
    int i0 = (blockIdx.x & 15) * TI;

    // one-time loads: s1 (256 vals) and FULL edge embedding (400 vals -> stride loop)
    sS1[tid] = g_s1[(size_t)(b * NN + i0) * HH + tid];
    for (int q = tid; q < NET * HH; q += 256)
        sEmb[(q >> 3) * 9 + (q & 7)] = emb[q];

    const float* gWhB = g_Wh + (size_t)b * NN * OUTF;
    unsigned int swhAddr = (unsigned int)__cvta_generic_to_shared(sWh);

    // prologue: async-load Wh tile 0 into buffer 0 (tile is 32KB contiguous)
#pragma unroll
    for (int q = 0; q < 8; q++) {
        unsigned int off = (unsigned int)(q * 256 + tid) * 16u;
        CP_ASYNC16(swhAddr + off, (const char*)gWhB + off);
    }
    CP_COMMIT();

    // prefetch adj/et/s2 for tile 0 into registers
    int tr  = tid >> 3;             // 0..31 (i-row within tile for adj/et)
    int tc4 = (tid & 7) << 2;       // j-chunk
    int4 adjR = *(const int4*)(adj + (size_t)(b * NN + i0 + tr) * NN + tc4);
    int4 etR  = *(const int4*)(et  + (size_t)(b * NN + i0 + tr) * NN + tc4);
    float s2R = g_s2[(size_t)b * NN * HH + tid];

    float acc[IPW][HH];
    float lsum[IPW][HH];
#pragma unroll
    for (int ii = 0; ii < IPW; ii++)
#pragma unroll
        for (int h = 0; h < HH; h++) { acc[ii][h] = 0.f; lsum[ii][h] = 0.f; }

    for (int jt = 0; jt < NN / TJ; jt++) {
        int cur = jt & 1;
        __syncthreads();            // previous consumers done with small arrays + sWh[cur]
        // store staged small tiles
        *(int4*)(sAdj + tr * 32 + tc4) = adjR;
        *(int4*)(sEt  + tr * 32 + tc4) = etR;
        sS2[(tid >> 3) * 9 + (tid & 7)] = s2R;
        // issue async Wh load for next tile into other buffer
        if (jt < 15) {
            unsigned int dstBase = swhAddr + (unsigned int)(cur ^ 1) * 32768u;
            const char* srcBase = (const char*)gWhB + (size_t)(jt + 1) * 32768u;
#pragma unroll
            for (int q = 0; q < 8; q++) {
                unsigned int off = (unsigned int)(q * 256 + tid) * 16u;
                CP_ASYNC16(dstBase + off, srcBase + off);
            }
            CP_COMMIT();
            CP_WAIT1();             // current tile's group complete
        } else {
            CP_WAIT0();
        }
        __syncthreads();            // small arrays + sWh[cur] visible to all
        // prefetch small tiles for next iteration (overlaps compute)
        if (jt < 15) {
            int j0n = (jt + 1) * TJ;
            adjR = *(const int4*)(adj + (size_t)(b * NN + i0 + tr) * NN + j0n + tc4);
            etR  = *(const int4*)(et  + (size_t)(b * NN + i0 + tr) * NN + j0n + tc4);
            s2R  = g_s2[(size_t)b * NN * HH + j0n * HH + tid];
        }

        // -------- score phase: lane = j --------
#pragma unroll
        for (int ii = 0; ii < IPW; ii++) {
            int il = (w << 2) + ii;
            int adjv = sAdj[(il << 5) + ln];
            int eb   = sEt[(il << 5) + ln] * 9;
            const float* s1p = sS1 + (il << 3);
            float* pdst = sP + (w << 10) + (ii << 8);   // [w][ii][h][32]
#pragma unroll
            for (int h = 0; h < HH; h++) {
                float e = s1p[h] + sS2[ln * 9 + h] + sEmb[eb + h];
                e = fmaf(0.2f, fminf(e, 0.f), fmaxf(e, 0.f));   // leaky relu 0.2
                float p = (adjv != 0) ? __expf(e) : 0.0f;       // |e|<~12: safe
                lsum[ii][h] += p;
                pdst[(h << 5) + ln] = p;
            }
        }
        __syncwarp();   // sP region is warp-private

        // -------- accumulate phase: lane = d --------
        const float* pw = sP + (w << 10);
        const float* whB = sWh + cur * 8192;
#pragma unroll
        for (int h = 0; h < HH; h++) {
            const float* whc = whB + (h << 5) + ln;
            const float* p0p = pw + (h << 5);
            const float* p1p = pw + 256 + (h << 5);
            const float* p2p = pw + 512 + (h << 5);
            const float* p3p = pw + 768 + (h << 5);
#pragma unroll
            for (int j4 = 0; j4 < 8; j4++) {
                float4 q0 = *(const float4*)(p0p + (j4 << 2));
                float4 q1 = *(const float4*)(p1p + (j4 << 2));
                float4 q2 = *(const float4*)(p2p + (j4 << 2));
                float4 q3 = *(const float4*)(p3p + (j4 << 2));
                float w0 = whc[((j4 << 2) + 0) * OUTF];
                float w1 = whc[((j4 << 2) + 1) * OUTF];
                float w2 = whc[((j4 << 2) + 2) * OUTF];
                float w3 = whc[((j4 << 2) + 3) * OUTF];
                acc[0][h] = fmaf(q0.x, w0, acc[0][h]);
                acc[1][h] = fmaf(q1.x, w0, acc[1][h]);
                acc[2][h] = fmaf(q2.x, w0, acc[2][h]);
                acc[3][h] = fmaf(q3.x, w0, acc[3][h]);
                acc[0][h] = fmaf(q0.y, w1, acc[0][h]);
                acc[1][h] = fmaf(q1.y, w1, acc[1][h]);
                acc[2][h] = fmaf(q2.y, w1, acc[2][h]);
                acc[3][h] = fmaf(q3.y, w1, acc[3][h]);
                acc[0][h] = fmaf(q0.z, w2, acc[0][h]);
                acc[1][h] = fmaf(q1.z, w2, acc[1][h]);
                acc[2][h] = fmaf(q2.z, w2, acc[2][h]);
                acc[3][h] = fmaf(q3.z, w2, acc[3][h]);
                acc[0][h] = fmaf(q0.w, w3, acc[0][h]);
                acc[1][h] = fmaf(q1.w, w3, acc[1][h]);
                acc[2][h] = fmaf(q2.w, w3, acc[2][h]);
                acc[3][h] = fmaf(q3.w, w3, acc[3][h]);
            }
        }
    }

    // -------- softmax denominators (reduce over lanes = j) --------
#pragma unroll
    for (int ii = 0; ii < IPW; ii++)
#pragma unroll
        for (int h = 0; h < HH; h++) {
            float v = lsum[ii][h];
            v += __shfl_xor_sync(0xffffffffu, v, 16);
            v += __shfl_xor_sync(0xffffffffu, v, 8);
            v += __shfl_xor_sync(0xffffffffu, v, 4);
            v += __shfl_xor_sync(0xffffffffu, v, 2);
            v += __shfl_xor_sync(0xffffffffu, v, 1);
            lsum[ii][h] = 1.0f / v;
        }

    float gr[HH], br[HH];
#pragma unroll
    for (int h = 0; h < HH; h++) {
        gr[h] = gamma[(h << 5) + ln];
        br[h] = beta[(h << 5) + ln];
    }

    // -------- LayerNorm + ELU + store --------
    int ibase = b * NN + i0 + (w << 2);
#pragma unroll
    for (int ii = 0; ii < IPW; ii++) {
        float y[HH];
        float s = 0.f;
#pragma unroll
        for (int h = 0; h < HH; h++) { y[h] = acc[ii][h] * lsum[ii][h]; s += y[h]; }
        s += __shfl_xor_sync(0xffffffffu, s, 16);
        s += __shfl_xor_sync(0xffffffffu, s, 8);
        s += __shfl_xor_sync(0xffffffffu, s, 4);
        s += __shfl_xor_sync(0xffffffffu, s, 2);
        s += __shfl_xor_sync(0xffffffffu, s, 1);
        float mu = s * 0.00390625f;   // /256
        float vs = 0.f;
#pragma unroll
        for (int h = 0; h < HH; h++) { float d = y[h] - mu; vs = fmaf(d, d, vs); }
        vs += __shfl_xor_sync(0xffffffffu, vs, 16);
        vs += __shfl_xor_sync(0xffffffffu, vs, 8);
        vs += __shfl_xor_sync(0xffffffffu, vs, 4);
        vs += __shfl_xor_sync(0xffffffffu, vs, 2);
        vs += __shfl_xor_sync(0xffffffffu, vs, 1);
        float rstd = rsqrtf(vs * 0.00390625f + 1e-5f);
        float* op = out + (size_t)(ibase + ii) * OUTF;
#pragma unroll
        for (int h = 0; h < HH; h++) {
            float o = fmaf((y[h] - mu) * rstd, gr[h], br[h]);
            o = (o > 0.f) ? o : expm1f(o);
            op[(h << 5) + ln] = o;
        }
    }
}

// ---------------------------------------------------------------------------
extern "C" void kernel_launch(void* const* d_in, const int* in_sizes, int n_in,
                              void* d_out, int out_size) {
    const float* x     = (const float*)d_in[0];
    const int*   adj   = (const int*)  d_in[1];
    const int*   etyp  = (const int*)  d_in[2];
    const float* W     = (const float*)d_in[3];
    const float* a1    = (const float*)d_in[4];
    const float* a2    = (const float*)d_in[5];
    const float* emb   = (const float*)d_in[6];
    const float* gamma = (const float*)d_in[7];
    const float* beta  = (const float*)d_in[8];
    float* out = (float*)d_out;

    dim3 gg(OUTF / 64, (BB * NN) / 128);
    gemm_kernel<<<gg, 256>>>(x, W);
    s_kernel<<<(BB * NN * HH + 255) / 256, 256>>>(a1, a2);
    cudaFuncSetAttribute(attn_kernel, cudaFuncAttributeMaxDynamicSharedMemorySize, SMEM_BYTES);
    attn_kernel<<<BB * (NN / TI), 256, SMEM_BYTES>>>(adj, etyp, emb, gamma, beta, out);
}